// round 8
// baseline (speedup 1.0000x reference)
#include <cuda_runtime.h>
#include <math.h>

#define BB 64
#define TT 1024
#define CC 512
#define TIE_W 1e-3f   // covers fp32 ulp of |score|<6400 (<=4.88e-4) + lp rounding

// device scratch (allocation-free per harness rules)
__device__ float2 g_m[BB * TT];    // .x = lp1 (= -L), .y = int bits: cls | (tie?1<<30)

// order-preserving float -> uint key (and inverse)
__device__ __forceinline__ unsigned fkey(float f) {
    unsigned b = __float_as_uint(f);
    return b ^ ((unsigned)((int)b >> 31) | 0x80000000u);
}
__device__ __forceinline__ float unkey(unsigned k) {
    unsigned b = (k & 0x80000000u) ? (k ^ 0x80000000u) : ~k;
    return __uint_as_float(b);
}

// ---------------------------------------------------------------------------
// Kernel A (SLIM): one warp per (b,t) row. No tie sidecar — just a flag bit.
// ---------------------------------------------------------------------------
__global__ __launch_bounds__(256, 5) void row_kernel(const float* __restrict__ logits) {
    int lane  = threadIdx.x & 31;
    int gwarp = blockIdx.x * 8 + (threadIdx.x >> 5);

    const float4* row = reinterpret_cast<const float4*>(logits + (size_t)gwarp * CC);
    float x[16];
#pragma unroll
    for (int i = 0; i < 4; i++) {
        float4 v = row[lane + 32 * i];  // coalesced LDG.128 x4, front-batched
        x[4*i+0] = v.x; x[4*i+1] = v.y; x[4*i+2] = v.z; x[4*i+3] = v.w;
    }

    // ---- row max via fmax tree + redux on monotonic key ----
    float m = x[0];
#pragma unroll
    for (int k = 1; k < 16; k++) m = fmaxf(m, x[k]);
    float M = unkey(__reduce_max_sync(0xffffffffu, fkey(m)));

    // ---- argmax class (min class on exact ties) via redux.min ----
    int cand = 0x7fffffff;
#pragma unroll
    for (int i = 3; i >= 0; i--)
#pragma unroll
        for (int j = 3; j >= 0; j--) {
            if (x[4*i+j] == M) cand = 128*i + 4*lane + j;  // ends at smallest match
        }
    int c1 = (int)__reduce_min_sync(0xffffffffu, (unsigned)cand);

    // ---- compensated fp32 sum of exp(x-M)  [bit-identical L to all passes] ----
    float s = 0.0f, c = 0.0f;
#pragma unroll
    for (int k = 0; k < 16; k++) {
        float y = __expf(x[k] - M) - c;
        float t = s + y;
        c = (t - s) - y;
        s = t;
    }
    c = -c;
#pragma unroll
    for (int off = 16; off > 0; off >>= 1) {
        float os = __shfl_xor_sync(0xffffffffu, s, off);
        float oc = __shfl_xor_sync(0xffffffffu, c, off);
        float t = s + os;
        float z = t - s;
        float e = (s - (t - z)) + (os - z);
        c = c + oc + e;
        s = t;
    }
    float L = logf(s) + c / s;

    // ---- tie window count via redux.add ----
    float thr = M - TIE_W;
    int cnt = 0;
#pragma unroll
    for (int k = 0; k < 16; k++) cnt += (x[k] >= thr);
    cnt = (int)__reduce_add_sync(0xffffffffu, (unsigned)cnt);

    if (lane == 0)
        g_m[gwarp] = make_float2(-L, __int_as_float(cnt < 2 ? c1 : (c1 | (1 << 30))));
}

// ---------------------------------------------------------------------------
// Kernel B: one block (256 thr) per batch.
//  stage -> thread-0 fp32 prefix chain -> tie rows: RECOMPUTE top-4 from
//  logits (one warp per flagged row, rare) -> parallel 3-pass CTC collapse.
// ---------------------------------------------------------------------------
__global__ __launch_bounds__(256) void scan_decode_kernel(const float* __restrict__ logits,
                                                          float* __restrict__ out_f,
                                                          int* __restrict__ out_i,
                                                          int mode) {
    int b    = blockIdx.x;
    int tid  = threadIdx.x;
    int lane = tid & 31;
    int warp = tid >> 5;
    unsigned lmask = (lane == 0) ? 0u : (0xffffffffu >> (32 - lane));

    __shared__ __align__(16) float s_lp[TT];
    __shared__ __align__(16) float s_pref[TT];   // written only at tie positions
    __shared__ int      s_cls[TT];
    __shared__ unsigned s_tiem[TT / 32];
    __shared__ unsigned s_keepm[TT / 32];
    __shared__ int s_tiet[64];                   // flagged positions (rare)
    __shared__ int s_ntie;
    __shared__ int s_segFirst[8], s_segLast[8], s_segCnt[8], s_segBase[8], s_segDrop[8];
    __shared__ float s_score;
    __shared__ int   s_len;

    if (tid == 0) s_ntie = 0;
    __syncthreads();

    // stage + tie-mask/list build + prefill output row with -1
#pragma unroll
    for (int k = 0; k < TT / 256; k++) {
        int t = tid + 256 * k;
        float2 mrec = g_m[b * TT + t];
        int cls = __float_as_int(mrec.y);
        bool tie = (cls & (1 << 30)) != 0;
        s_lp[t]  = mrec.x;
        s_cls[t] = cls;
        unsigned tm = __ballot_sync(0xffffffffu, tie);
        if (lane == 0) s_tiem[8 * k + warp] = tm;
        if (tie) {
            int slot = atomicAdd(&s_ntie, 1);
            if (slot < 64) s_tiet[slot] = t;
        }
        if (mode == 0) out_f[b * TT + t] = -1.0f;
        else           out_i[b * TT + t] = -1;
    }
    __syncthreads();

    // sequential fp32 prefix chain, loads batched ahead of the FADD chain
    if (tid == 0) {
        float s = 0.0f;
        for (int blk = 0; blk < TT; blk += 32) {
            float v[32];
            const float4* lp4 = reinterpret_cast<const float4*>(s_lp + blk);
#pragma unroll
            for (int q = 0; q < 8; q++) {
                float4 f = lp4[q];
                v[4*q+0] = f.x; v[4*q+1] = f.y; v[4*q+2] = f.z; v[4*q+3] = f.w;
            }
            unsigned tm = s_tiem[blk >> 5];
            if (tm == 0u) {
#pragma unroll
                for (int j = 0; j < 32; j++) s = __fadd_rn(s, v[j]);
            } else {
#pragma unroll
                for (int j = 0; j < 32; j++) {
                    if (tm & (1u << j)) s_pref[blk + j] = s;
                    s = __fadd_rn(s, v[j]);
                }
            }
        }
        s_score = s;
    }
    __syncthreads();

    // ---- tie resolution by RECOMPUTE (one warp per flagged row, rare) ----
    {
        int ntie = min(s_ntie, 64);
        for (int idx = warp; idx < ntie; idx += 8) {
            int t = s_tiet[idx];
            const float4* row = reinterpret_cast<const float4*>(logits + (size_t)(b * TT + t) * CC);
            float x[16];
#pragma unroll
            for (int i = 0; i < 4; i++) {
                float4 v = row[lane + 32 * i];
                x[4*i+0] = v.x; x[4*i+1] = v.y; x[4*i+2] = v.z; x[4*i+3] = v.w;
            }
            float m = x[0];
#pragma unroll
            for (int k = 1; k < 16; k++) m = fmaxf(m, x[k]);
            float M = unkey(__reduce_max_sync(0xffffffffu, fkey(m)));

            // masked top-4 (desc value, min class on exact ties) — identical to prior rounds
            unsigned sel = 0u;
            float tv[4]; int tc[4];
#pragma unroll
            for (int k = 0; k < 4; k++) {
                float bv = -3.4e38f; int bc = 0x7fffffff;
#pragma unroll
                for (int i = 0; i < 4; i++)
#pragma unroll
                    for (int j = 0; j < 4; j++) {
                        int slot = i * 4 + j;
                        if (!((sel >> slot) & 1u)) {
                            float xv = x[slot];
                            if (xv > bv) { bv = xv; bc = 128*i + 4*lane + j; }
                        }
                    }
#pragma unroll
                for (int off = 16; off > 0; off >>= 1) {
                    float ov = __shfl_xor_sync(0xffffffffu, bv, off);
                    int   oc = __shfl_xor_sync(0xffffffffu, bc, off);
                    if (ov > bv || (ov == bv && oc < bc)) { bv = ov; bc = oc; }
                }
                tv[k] = bv; tc[k] = bc;
                if (((bc >> 2) & 31) == lane) {
                    int i = bc >> 7, j = bc & 3;
                    sel |= 1u << (i * 4 + j);
                }
            }
            if (lane == 0) {
                float L   = -s_lp[t];                         // lp1 == -L
                float s   = s_pref[t];
                float r   = __fadd_rn(s, s_lp[t]);
                int   ch  = tc[0];
                float lp1 = __fadd_rn(__fadd_rn(tv[1], -M), -L);
                float lp2 = __fadd_rn(__fadd_rn(tv[2], -M), -L);
                float lp3 = __fadd_rn(__fadd_rn(tv[3], -M), -L);
                if (__fadd_rn(s, lp1) == r && tc[1] < ch) ch = tc[1];
                if (__fadd_rn(s, lp2) == r && tc[2] < ch) ch = tc[2];
                if (__fadd_rn(s, lp3) == r && tc[3] < ch) ch = tc[3];
                s_cls[t] = ch;
            }
        }
    }
    __syncthreads();

    // ---- pass 1: each warp builds keep masks for its 128-elem segment ----
    {
        int carryPrev = -1;
        int firstCls  = -1;
        int cnt = 0;
#pragma unroll
        for (int j = 0; j < 4; j++) {
            int t   = 128 * warp + 32 * j + lane;
            int cls = s_cls[t];
            bool nb = (cls != 0);

            unsigned nbm   = __ballot_sync(0xffffffffu, nb);
            unsigned below = nbm & lmask;
            int src = 31 - __clz(below);
            int pc  = __shfl_sync(0xffffffffu, cls, src & 31);
            int myPrev = below ? pc : carryPrev;

            bool keep = nb && (cls != myPrev);
            unsigned km = __ballot_sync(0xffffffffu, keep);
            if (lane == 0) s_keepm[4 * warp + j] = km;
            cnt += __popc(km);
            if (nbm) {
                int last = __shfl_sync(0xffffffffu, cls, 31 - __clz(nbm));
                int frst = __shfl_sync(0xffffffffu, cls, __ffs(nbm) - 1);
                carryPrev = last;
                if (firstCls == -1) firstCls = frst;
            }
        }
        if (lane == 0) {
            s_segFirst[warp] = firstCls;
            s_segLast[warp]  = carryPrev;
            s_segCnt[warp]   = cnt;
        }
    }
    __syncthreads();

    // ---- pass 2: thread 0 composes the 8 segment carries ----
    if (tid == 0) {
        int prev = -1, base = 0;
        for (int w = 0; w < 8; w++) {
            int drop = (s_segFirst[w] != -1 && s_segFirst[w] == prev) ? 1 : 0;
            s_segBase[w] = base;
            s_segDrop[w] = drop;
            base += s_segCnt[w] - drop;
            if (s_segLast[w] != -1) prev = s_segLast[w];
        }
        s_len = base;
    }
    __syncthreads();

    // clear dropped first-keep bit (first keep bit == first non-blank)
    if (lane == 0 && s_segDrop[warp]) {
#pragma unroll
        for (int j = 0; j < 4; j++) {
            unsigned km = s_keepm[4 * warp + j];
            if (km) { s_keepm[4 * warp + j] = km & (km - 1); break; }
        }
    }
    __syncwarp();

    // ---- pass 3: compacted writes ----
    {
        int running = s_segBase[warp];
#pragma unroll
        for (int j = 0; j < 4; j++) {
            int t = 128 * warp + 32 * j + lane;
            unsigned km = s_keepm[4 * warp + j];
            bool keep = (km >> lane) & 1u;
            int dst = running + __popc(km & lmask);
            if (keep) {
                int cls = s_cls[t];
                if (mode == 0) out_f[b * TT + dst] = (float)cls;
                else           out_i[b * TT + dst] = cls;
            }
            running += __popc(km);
        }
    }

    if (tid == 0 && mode == 0) {
        out_f[BB * TT + b]      = (float)s_len;   // lengths
        out_f[BB * TT + BB + b] = s_score;        // scores[:,0]
    }
}

extern "C" void kernel_launch(void* const* d_in, const int* in_sizes, int n_in,
                              void* d_out, int out_size) {
    const float* logits = (const float*)d_in[0];

    row_kernel<<<(BB * TT) / 8, 256>>>(logits);

    int mode = (out_size == BB * TT) ? 1 : 0;
    scan_decode_kernel<<<BB, 256>>>(logits, (float*)d_out, (int*)d_out, mode);
}

// round 9
// speedup vs baseline: 1.0576x; 1.0576x over previous
#include <cuda_runtime.h>
#include <math.h>

#define BB 64
#define TT 1024
#define CC 512
#define TIE_W 1e-3f   // covers fp32 ulp of |score|<6400 (<=4.88e-4) + lp rounding

// device scratch (allocation-free per harness rules)
__device__ float2 g_m[BB * TT];    // .x = lp1 (= -L), .y = int bits: cls | (tie?1<<30)

// order-preserving float -> uint key (and inverse)
__device__ __forceinline__ unsigned fkey(float f) {
    unsigned b = __float_as_uint(f);
    return b ^ ((unsigned)((int)b >> 31) | 0x80000000u);
}
__device__ __forceinline__ float unkey(unsigned k) {
    unsigned b = (k & 0x80000000u) ? (k ^ 0x80000000u) : ~k;
    return __uint_as_float(b);
}

// ---------------------------------------------------------------------------
// Kernel A (slim, 6 blocks/SM): one warp per (b,t) row. Flag bit only.
// ---------------------------------------------------------------------------
__global__ __launch_bounds__(256, 6) void row_kernel(const float* __restrict__ logits) {
    int lane  = threadIdx.x & 31;
    int gwarp = blockIdx.x * 8 + (threadIdx.x >> 5);

    const float4* row = reinterpret_cast<const float4*>(logits + (size_t)gwarp * CC);
    float x[16];
#pragma unroll
    for (int i = 0; i < 4; i++) {
        float4 v = __ldcs(row + lane + 32 * i);  // streaming, coalesced
        x[4*i+0] = v.x; x[4*i+1] = v.y; x[4*i+2] = v.z; x[4*i+3] = v.w;
    }

    // ---- row max via fmax tree + redux on monotonic key ----
    float m = x[0];
#pragma unroll
    for (int k = 1; k < 16; k++) m = fmaxf(m, x[k]);
    float M = unkey(__reduce_max_sync(0xffffffffu, fkey(m)));

    // ---- argmax class (min class on exact ties) via redux.min ----
    int cand = 0x7fffffff;
#pragma unroll
    for (int i = 3; i >= 0; i--)
#pragma unroll
        for (int j = 3; j >= 0; j--) {
            if (x[4*i+j] == M) cand = 128*i + 4*lane + j;  // ends at smallest match
        }
    int c1 = (int)__reduce_min_sync(0xffffffffu, (unsigned)cand);

    // ---- compensated fp32 sum of exp(x-M)  [bit-identical L — NEVER touch] ----
    float s = 0.0f, c = 0.0f;
#pragma unroll
    for (int k = 0; k < 16; k++) {
        float y = __expf(x[k] - M) - c;
        float t = s + y;
        c = (t - s) - y;
        s = t;
    }
    c = -c;
#pragma unroll
    for (int off = 16; off > 0; off >>= 1) {
        float os = __shfl_xor_sync(0xffffffffu, s, off);
        float oc = __shfl_xor_sync(0xffffffffu, c, off);
        float t = s + os;
        float z = t - s;
        float e = (s - (t - z)) + (os - z);
        c = c + oc + e;
        s = t;
    }
    float L = logf(s) + c / s;

    // ---- tie window count via redux.add ----
    float thr = M - TIE_W;
    int cnt = 0;
#pragma unroll
    for (int k = 0; k < 16; k++) cnt += (x[k] >= thr);
    cnt = (int)__reduce_add_sync(0xffffffffu, (unsigned)cnt);

    if (lane == 0)
        g_m[gwarp] = make_float2(-L, __int_as_float(cnt < 2 ? c1 : (c1 | (1 << 30))));
}

// ---------------------------------------------------------------------------
// Kernel B: one block (256 thr) per batch.
//  stage (float4) -> [thread 0: fp32 prefix chain] OVERLAPPED WITH
//  [warps 1-7: recompute tie candidates from logits] -> cheap tie decision
//  -> parallel 3-pass CTC collapse.
// ---------------------------------------------------------------------------
__global__ __launch_bounds__(256) void scan_decode_kernel(const float* __restrict__ logits,
                                                          float* __restrict__ out_f,
                                                          int* __restrict__ out_i,
                                                          int mode) {
    int b    = blockIdx.x;
    int tid  = threadIdx.x;
    int lane = tid & 31;
    int warp = tid >> 5;
    unsigned lmask = (lane == 0) ? 0u : (0xffffffffu >> (32 - lane));

    __shared__ __align__(16) float s_lp[TT];
    __shared__ __align__(16) float s_pref[TT];   // written only at tie positions
    __shared__ int      s_cls[TT];
    __shared__ unsigned s_tiem[TT / 32];
    __shared__ unsigned s_keepm[TT / 32];
    __shared__ int    s_tiet[64];                // flagged positions (rare)
    __shared__ float4 s_tlp[64];                 // recomputed lp1..lp3 (x unused)
    __shared__ int4   s_tc4[64];                 // recomputed classes
    __shared__ int s_ntie;
    __shared__ int s_segFirst[8], s_segLast[8], s_segCnt[8], s_segBase[8], s_segDrop[8];
    __shared__ float s_score;
    __shared__ int   s_len;

    if (tid == 0) s_ntie = 0;
    __syncthreads();

    // stage (vectorized: 2 records per float4) + tie list + prefill -1
#pragma unroll
    for (int k = 0; k < TT / 512; k++) {
        int t2 = tid + 256 * k;                  // record pair index
        float4 r = reinterpret_cast<const float4*>(g_m)[b * (TT / 2) + t2];
        int t = 2 * t2;
        int cls0 = __float_as_int(r.y);
        int cls1 = __float_as_int(r.w);
        s_lp[t]      = r.x;  s_lp[t + 1]  = r.z;
        s_cls[t]     = cls0; s_cls[t + 1] = cls1;
        bool tie0 = (cls0 & (1 << 30)) != 0;
        bool tie1 = (cls1 & (1 << 30)) != 0;
        unsigned tm0 = __ballot_sync(0xffffffffu, tie0);
        unsigned tm1 = __ballot_sync(0xffffffffu, tie1);
        if (lane == 0) {
            // interleave lane pairs into two 32-bit masks for chunks 2w, 2w+1... 
            // simpler: store per-32 masks by recomputing below
        }
        // build per-32-chunk tie masks exactly (chunk = t/32): lanes 0..15 cover
        // even/odd within chunk 2*(8k+warp) ... use explicit scatter instead:
        if (tie0) { int slot = atomicAdd(&s_ntie, 1); if (slot < 64) s_tiet[slot] = t; }
        if (tie1) { int slot = atomicAdd(&s_ntie, 1); if (slot < 64) s_tiet[slot] = t + 1; }
        (void)tm0; (void)tm1;
        if (mode == 0) { out_f[b * TT + t] = -1.0f; out_f[b * TT + t + 1] = -1.0f; }
        else           { out_i[b * TT + t] = -1;    out_i[b * TT + t + 1] = -1;    }
    }
    __syncthreads();

    // rebuild 32-chunk tie masks from s_cls (cheap, parallel)
    {
        int chunk = tid >> 5;                    // 8 chunks per pass
#pragma unroll
        for (int k = 0; k < TT / 256; k++) {
            int cidx = chunk + 8 * k;
            int cls = s_cls[cidx * 32 + lane];
            unsigned tm = __ballot_sync(0xffffffffu, (cls & (1 << 30)) != 0);
            if (lane == 0) s_tiem[cidx] = tm;
        }
    }
    __syncthreads();

    int ntie = min(s_ntie, 64);

    // ===== OVERLAPPED: thread 0 chain  ||  warps 1-7 tie recompute =====
    if (tid == 0) {
        float s = 0.0f;
        for (int blk = 0; blk < TT; blk += 32) {
            float v[32];
            const float4* lp4 = reinterpret_cast<const float4*>(s_lp + blk);
#pragma unroll
            for (int q = 0; q < 8; q++) {
                float4 f = lp4[q];
                v[4*q+0] = f.x; v[4*q+1] = f.y; v[4*q+2] = f.z; v[4*q+3] = f.w;
            }
            unsigned tm = s_tiem[blk >> 5];
            if (tm == 0u) {
#pragma unroll
                for (int j = 0; j < 32; j++) s = __fadd_rn(s, v[j]);
            } else {
#pragma unroll
                for (int j = 0; j < 32; j++) {
                    if (tm & (1u << j)) s_pref[blk + j] = s;
                    s = __fadd_rn(s, v[j]);
                }
            }
        }
        s_score = s;
    } else if (warp >= 1) {
        for (int idx = warp - 1; idx < ntie; idx += 7) {
            int t = s_tiet[idx];
            const float4* row = reinterpret_cast<const float4*>(logits + (size_t)(b * TT + t) * CC);
            float x[16];
#pragma unroll
            for (int i = 0; i < 4; i++) {
                float4 v = row[lane + 32 * i];
                x[4*i+0] = v.x; x[4*i+1] = v.y; x[4*i+2] = v.z; x[4*i+3] = v.w;
            }
            float m = x[0];
#pragma unroll
            for (int k = 1; k < 16; k++) m = fmaxf(m, x[k]);
            float M = unkey(__reduce_max_sync(0xffffffffu, fkey(m)));

            // masked top-4 (desc value, min class on ties) — identical arithmetic
            unsigned sel = 0u;
            float tv[4]; int tc[4];
#pragma unroll
            for (int k = 0; k < 4; k++) {
                float bv = -3.4e38f; int bc = 0x7fffffff;
#pragma unroll
                for (int i = 0; i < 4; i++)
#pragma unroll
                    for (int j = 0; j < 4; j++) {
                        int slot = i * 4 + j;
                        if (!((sel >> slot) & 1u)) {
                            float xv = x[slot];
                            if (xv > bv) { bv = xv; bc = 128*i + 4*lane + j; }
                        }
                    }
#pragma unroll
                for (int off = 16; off > 0; off >>= 1) {
                    float ov = __shfl_xor_sync(0xffffffffu, bv, off);
                    int   oc = __shfl_xor_sync(0xffffffffu, bc, off);
                    if (ov > bv || (ov == bv && oc < bc)) { bv = ov; bc = oc; }
                }
                tv[k] = bv; tc[k] = bc;
                if (((bc >> 2) & 31) == lane) {
                    int i = bc >> 7, j = bc & 3;
                    sel |= 1u << (i * 4 + j);
                }
            }
            if (lane == 0) {
                float L = -s_lp[t];                          // lp1 == -L
                float4 lp;
                lp.x = 0.0f;
                lp.y = __fadd_rn(__fadd_rn(tv[1], -M), -L);
                lp.z = __fadd_rn(__fadd_rn(tv[2], -M), -L);
                lp.w = __fadd_rn(__fadd_rn(tv[3], -M), -L);
                s_tlp[idx] = lp;
                s_tc4[idx] = make_int4(tc[0], tc[1], tc[2], tc[3]);
            }
        }
    }
    __syncthreads();

    // cheap tie decision (needs exact prefix s)
    if (tid < ntie) {
        int t = s_tiet[tid];
        float4 lp = s_tlp[tid];
        int4   cc = s_tc4[tid];
        float  s  = s_pref[t];
        float  r  = __fadd_rn(s, s_lp[t]);      // s + lp1 (lp1 = -L)
        int ch = cc.x;
        if (__fadd_rn(s, lp.y) == r && cc.y < ch) ch = cc.y;
        if (__fadd_rn(s, lp.z) == r && cc.z < ch) ch = cc.z;
        if (__fadd_rn(s, lp.w) == r && cc.w < ch) ch = cc.w;
        s_cls[t] = ch;
    }
    __syncthreads();

    // ---- pass 1: each warp builds keep masks for its 128-elem segment ----
    {
        int carryPrev = -1;
        int firstCls  = -1;
        int cnt = 0;
#pragma unroll
        for (int j = 0; j < 4; j++) {
            int t   = 128 * warp + 32 * j + lane;
            int cls = s_cls[t] & 0x3FFFFFFF;     // strip flag (cap-overflow safety)
            bool nb = (cls != 0);

            unsigned nbm   = __ballot_sync(0xffffffffu, nb);
            unsigned below = nbm & lmask;
            int src = 31 - __clz(below);
            int pc  = __shfl_sync(0xffffffffu, cls, src & 31);
            int myPrev = below ? pc : carryPrev;

            bool keep = nb && (cls != myPrev);
            unsigned km = __ballot_sync(0xffffffffu, keep);
            if (lane == 0) s_keepm[4 * warp + j] = km;
            cnt += __popc(km);
            if (nbm) {
                int last = __shfl_sync(0xffffffffu, cls, 31 - __clz(nbm));
                int frst = __shfl_sync(0xffffffffu, cls, __ffs(nbm) - 1);
                carryPrev = last;
                if (firstCls == -1) firstCls = frst;
            }
        }
        if (lane == 0) {
            s_segFirst[warp] = firstCls;
            s_segLast[warp]  = carryPrev;
            s_segCnt[warp]   = cnt;
        }
    }
    __syncthreads();

    // ---- pass 2: thread 0 composes the 8 segment carries ----
    if (tid == 0) {
        int prev = -1, base = 0;
        for (int w = 0; w < 8; w++) {
            int drop = (s_segFirst[w] != -1 && s_segFirst[w] == prev) ? 1 : 0;
            s_segBase[w] = base;
            s_segDrop[w] = drop;
            base += s_segCnt[w] - drop;
            if (s_segLast[w] != -1) prev = s_segLast[w];
        }
        s_len = base;
    }
    __syncthreads();

    // clear dropped first-keep bit (first keep bit == first non-blank)
    if (lane == 0 && s_segDrop[warp]) {
#pragma unroll
        for (int j = 0; j < 4; j++) {
            unsigned km = s_keepm[4 * warp + j];
            if (km) { s_keepm[4 * warp + j] = km & (km - 1); break; }
        }
    }
    __syncwarp();

    // ---- pass 3: compacted writes ----
    {
        int running = s_segBase[warp];
#pragma unroll
        for (int j = 0; j < 4; j++) {
            int t = 128 * warp + 32 * j + lane;
            unsigned km = s_keepm[4 * warp + j];
            bool keep = (km >> lane) & 1u;
            int dst = running + __popc(km & lmask);
            if (keep) {
                int cls = s_cls[t] & 0x3FFFFFFF;
                if (mode == 0) out_f[b * TT + dst] = (float)cls;
                else           out_i[b * TT + dst] = cls;
            }
            running += __popc(km);
        }
    }

    if (tid == 0 && mode == 0) {
        out_f[BB * TT + b]      = (float)s_len;   // lengths
        out_f[BB * TT + BB + b] = s_score;        // scores[:,0]
    }
}

extern "C" void kernel_launch(void* const* d_in, const int* in_sizes, int n_in,
                              void* d_out, int out_size) {
    const float* logits = (const float*)d_in[0];

    row_kernel<<<(BB * TT) / 8, 256>>>(logits);

    int mode = (out_size == BB * TT) ? 1 : 0;
    scan_decode_kernel<<<BB, 256>>>(logits, (float*)d_out, (int*)d_out, mode);
}